// round 10
// baseline (speedup 1.0000x reference)
#include <cuda_runtime.h>
#include <cuda_fp16.h>
#include <math.h>
#include <stdint.h>

#define NB 4
#define NP 8
#define NN 512
#define DM 128
#define NH 4
#define DK 32
#define NT 3
#define NROWS (NB*NP*NN)     // 16384
#define MAXNNZ 128
#define LDP 132              // smem row stride (floats) for GEMM tiles

// Scratch (device globals). fp16 intermediates to halve HBM traffic.
__device__ __half g_qkv[9][NROWS][DM];   // [t*3 + {Q,K,V}][row][d]
__device__ __half g_attn[NT][NROWS][DM]; // per-t attention output (fp16)
__device__ int    g_cnt[NT][NN];
__device__ int    g_rank[NT][NN];        // row n -> rank (sorted by cnt asc)
__device__ int    g_rowOfRank[NT][NN];   // rank -> row n
__device__ int    g_nnzR[NT][NN];        // cnt indexed by rank
__device__ int    g_colsT[NT][MAXNNZ][NN];   // [t][i][rank] -> coalesced over rank
__device__ float  g_valsT[NT][MAXNNZ][NN];

__constant__ int c_which[NT] = {0, 1, 3};

// ---------------------------------------------------------------------------
__device__ __forceinline__ uint32_t smem_u32(const void* p) {
    uint32_t a;
    asm("{ .reg .u64 t; cvta.to.shared.u64 t, %1; cvt.u32.u64 %0, t; }" : "=r"(a) : "l"(p));
    return a;
}
__device__ __forceinline__ void cp16(uint32_t dst, const void* src) {
    asm volatile("cp.async.ca.shared.global [%0], [%1], 16;" :: "r"(dst), "l"(src));
}
#define CP_COMMIT() asm volatile("cp.async.commit_group;" ::: "memory")
#define CP_WAIT0()  asm volatile("cp.async.wait_group 0;" ::: "memory")

__device__ __forceinline__ uint32_t f2tf32(float f) {
    uint32_t r; asm("cvt.rna.tf32.f32 %0, %1;" : "=r"(r) : "f"(f)); return r;
}
__device__ __forceinline__ uint32_t pack_h2(float a, float b) {
    __half2 h = __floats2half2_rn(a, b);
    return *(uint32_t*)&h;
}
// m16n8k8 tf32 MMA, D += A*B (row x col)
__device__ __forceinline__ void mma8(float d[4], const uint32_t a[4], const uint32_t b[2]) {
    asm volatile("mma.sync.aligned.m16n8k8.row.col.f32.tf32.tf32.f32 "
        "{%0,%1,%2,%3}, {%4,%5,%6,%7}, {%8,%9}, {%0,%1,%2,%3};"
        : "+f"(d[0]), "+f"(d[1]), "+f"(d[2]), "+f"(d[3])
        : "r"(a[0]), "r"(a[1]), "r"(a[2]), "r"(a[3]), "r"(b[0]), "r"(b[1]));
}

// ===========================================================================
// Kernel 1a: count nonzeros per selected-tm row
// ===========================================================================
__global__ void count_kernel(const float* __restrict__ tmall) {
    int wg   = (blockIdx.x * blockDim.x + threadIdx.x) >> 5;
    int lane = threadIdx.x & 31;
    if (wg >= NT * NN) return;
    int t = wg / NN, n = wg % NN;
    const float* row = tmall + ((size_t)c_which[t] * NN + n) * NN;
    int cnt = 0;
    for (int base = 0; base < NN; base += 32)
        cnt += __popc(__ballot_sync(0xffffffffu, row[base + lane] != 0.0f));
    if (lane == 0) g_cnt[t][n] = cnt < MAXNNZ ? cnt : MAXNNZ;
}

// ===========================================================================
// Kernel 1b: rank rows by cnt (stable, deterministic). Block per t.
// ===========================================================================
__global__ void rank_kernel() {
    __shared__ int sc[NN];
    int t = blockIdx.x, n = threadIdx.x;
    sc[n] = g_cnt[t][n];
    __syncthreads();
    int c = sc[n], r = 0;
    for (int m = 0; m < NN; m++) {
        int cm = sc[m];
        r += (cm < c) || (cm == c && m < n);
    }
    g_rank[t][n] = r;
    g_rowOfRank[t][r] = n;
    g_nnzR[t][r] = c;
}

// ===========================================================================
// Kernel 1c: fill transposed CSR at rank column
// ===========================================================================
__global__ void fill_kernel(const float* __restrict__ tmall) {
    int wg   = (blockIdx.x * blockDim.x + threadIdx.x) >> 5;
    int lane = threadIdx.x & 31;
    if (wg >= NT * NN) return;
    int t = wg / NN, n = wg % NN;
    int rk = g_rank[t][n];
    const float* row = tmall + ((size_t)c_which[t] * NN + n) * NN;
    int cnt = 0;
    for (int base = 0; base < NN; base += 32) {
        float v = row[base + lane];
        unsigned b = __ballot_sync(0xffffffffu, v != 0.0f);
        if (v != 0.0f) {
            int pos = cnt + __popc(b & ((1u << lane) - 1u));
            if (pos < MAXNNZ) { g_colsT[t][pos][rk] = base + lane; g_valsT[t][pos][rk] = v; }
        }
        cnt += __popc(b);
    }
}

// ===========================================================================
// Kernel 2: QKV projections via tf32 mma.sync, grid = (256 tiles, 9 slots),
// 256 threads / 8 warps, 2 CTAs/SM, cp.async staging. Output stored fp16.
// ===========================================================================
__global__ void __launch_bounds__(256, 2)
qkv_mma_kernel(const float* __restrict__ X,
               const float* __restrict__ Wq,
               const float* __restrict__ Wk,
               const float* __restrict__ Wv) {
    extern __shared__ uint32_t sm[];
    uint32_t* Xs = sm;                // [64][LDP]
    uint32_t* Ws = sm + 64 * LDP;     // [128][LDP]
    int tid = threadIdx.x, lane = tid & 31, wid = tid >> 5;
    int mw = wid & 1, nw = wid >> 1;
    int g = lane >> 2, q = lane & 3;
    int slot = blockIdx.y;
    int row0 = blockIdx.x * 64;

    const float* Wb[3] = {Wq, Wk, Wv};
    const float* W = Wb[slot % 3] + (size_t)(slot / 3) * DM * DM;

    uint32_t xs_u = smem_u32(Xs), ws_u = smem_u32(Ws);
    for (int i = tid; i < 64 * 32; i += 256) {
        int r = i >> 5, k = (i & 31) << 2;
        cp16(xs_u + (r * LDP + k) * 4, X + (size_t)(row0 + r) * DM + k);
    }
    for (int i = tid; i < 128 * 32; i += 256) {
        int r = i >> 5, k = (i & 31) << 2;
        cp16(ws_u + (r * LDP + k) * 4, W + (size_t)r * DM + k);
    }
    CP_COMMIT(); CP_WAIT0();
    __syncthreads();

    const uint32_t* abase = Xs + (mw * 32 + g) * LDP + q;
    const uint32_t* bbase = Ws + (nw * 32 + g) * LDP + q;

    float acc[2][4][4];
    #pragma unroll
    for (int t2 = 0; t2 < 2; t2++)
        #pragma unroll
        for (int j = 0; j < 4; j++)
            #pragma unroll
            for (int e = 0; e < 4; e++) acc[t2][j][e] = 0.f;

    #pragma unroll 4
    for (int ks = 0; ks < 16; ks++) {
        int k0 = ks * 8;
        uint32_t a[2][4];
        #pragma unroll
        for (int t2 = 0; t2 < 2; t2++) {
            const uint32_t* ap = abase + t2 * 16 * LDP + k0;
            a[t2][0] = ap[0]; a[t2][1] = ap[8 * LDP];
            a[t2][2] = ap[4]; a[t2][3] = ap[8 * LDP + 4];
        }
        #pragma unroll
        for (int j = 0; j < 4; j++) {
            const uint32_t* bp = bbase + j * 8 * LDP + k0;
            uint32_t b[2]; b[0] = bp[0]; b[1] = bp[4];
            mma8(acc[0][j], a[0], b);
            mma8(acc[1][j], a[1], b);
        }
    }
    __half* outh = &g_qkv[slot][row0][0];
    #pragma unroll
    for (int t2 = 0; t2 < 2; t2++) {
        int r = mw * 32 + t2 * 16 + g;
        #pragma unroll
        for (int j = 0; j < 4; j++) {
            int c = nw * 32 + j * 8 + q * 2;
            *(uint32_t*)(outh + (size_t)r * DM + c)       = pack_h2(acc[t2][j][0], acc[t2][j][1]);
            *(uint32_t*)(outh + (size_t)(r + 8) * DM + c) = pack_h2(acc[t2][j][2], acc[t2][j][3]);
        }
    }
}

// ===========================================================================
// Kernel 3: sparse-masked attention. Block = (t,bp,h), 512 threads, thread =
// rank (rows sorted by nnz -> uniform warp iteration counts). K/V read fp16
// from g_qkv, converted into the R4 fp32 SMEM layout (stride-32, lane-rotated
// float4 reads -> deterministic 4-phase crossbar). Direct exp; scale folded
// into Q; coalesced rank-indexed CSR; fp16 output.
// ===========================================================================
__global__ void __launch_bounds__(512, 1)
attn_kernel() {
    extern __shared__ float smf[];
    float* Ks = smf;               // [512][32]
    float* Vs = smf + 512 * 32;    // [512][32]
    int tid = threadIdx.x;
    int h = blockIdx.x;
    int t = blockIdx.y >> 5, bp = blockIdx.y & 31;

    const __half* Kg = &g_qkv[t * 3 + 1][(size_t)bp * NN][0];
    const __half* Vg = &g_qkv[t * 3 + 2][(size_t)bp * NN][0];
    for (int i = tid; i < 512 * 4; i += 512) {
        int m = i >> 2, c = i & 3;
        uint4 kk = *(const uint4*)(Kg + (size_t)m * DM + h * DK + c * 8);
        float2 f0 = __half22float2(*(__half2*)&kk.x);
        float2 f1 = __half22float2(*(__half2*)&kk.y);
        float2 f2 = __half22float2(*(__half2*)&kk.z);
        float2 f3 = __half22float2(*(__half2*)&kk.w);
        *(float4*)(Ks + m * 32 + c * 8)     = make_float4(f0.x, f0.y, f1.x, f1.y);
        *(float4*)(Ks + m * 32 + c * 8 + 4) = make_float4(f2.x, f2.y, f3.x, f3.y);
        uint4 vv = *(const uint4*)(Vg + (size_t)m * DM + h * DK + c * 8);
        f0 = __half22float2(*(__half2*)&vv.x);
        f1 = __half22float2(*(__half2*)&vv.y);
        f2 = __half22float2(*(__half2*)&vv.z);
        f3 = __half22float2(*(__half2*)&vv.w);
        *(float4*)(Vs + m * 32 + c * 8)     = make_float4(f0.x, f0.y, f1.x, f1.y);
        *(float4*)(Vs + m * 32 + c * 8 + 4) = make_float4(f2.x, f2.y, f3.x, f3.y);
    }
    __syncthreads();

    int rk = tid;
    int n = g_rowOfRank[t][rk];
    int gn = bp * NN + n;
    int rot = tid & 7;
    const float scale = 0.17677669529663687f;   // 1/sqrt(32), folded into Q
    float4 qr[8];
    const __half* Qg = &g_qkv[t * 3 + 0][gn][h * DK];
    #pragma unroll
    for (int j = 0; j < 8; j++) {
        int jj = (j + rot) & 7;
        uint2 qv = *(const uint2*)(Qg + jj * 4);
        float2 a = __half22float2(*(__half2*)&qv.x);
        float2 b = __half22float2(*(__half2*)&qv.y);
        qr[j] = make_float4(a.x * scale, a.y * scale, b.x * scale, b.y * scale);
    }
    int cnt = g_nnzR[t][rk];
    float Z = 0.f;
    float4 av[8];
    #pragma unroll
    for (int j = 0; j < 8; j++) av[j] = make_float4(0.f, 0.f, 0.f, 0.f);

    for (int i = 0; i < cnt; i++) {
        int m = g_colsT[t][i][rk];       // coalesced: lanes = consecutive ranks
        float tv = g_valsT[t][i][rk];
        const float* kb = Ks + m * 32;
        float s = 0.f;
        #pragma unroll
        for (int j = 0; j < 8; j++) {
            int jj = (j + rot) & 7;
            float4 k4 = *(const float4*)(kb + jj * 4);
            s += qr[j].x * k4.x + qr[j].y * k4.y + qr[j].z * k4.z + qr[j].w * k4.w;
        }
        float e = __expf(s);
        Z += e;
        float we = tv * e;
        const float* vb = Vs + m * 32;
        #pragma unroll
        for (int j = 0; j < 8; j++) {
            int jj = (j + rot) & 7;
            float4 v4 = *(const float4*)(vb + jj * 4);
            av[j].x += we * v4.x;
            av[j].y += we * v4.y;
            av[j].z += we * v4.z;
            av[j].w += we * v4.w;
        }
    }
    float inv = 1.f / Z;
    __half* outh = &g_attn[t][gn][h * DK];
    #pragma unroll
    for (int j = 0; j < 8; j++) {
        int jj = (j + rot) & 7;
        uint2 p = make_uint2(pack_h2(av[j].x * inv, av[j].y * inv),
                             pack_h2(av[j].z * inv, av[j].w * inv));
        *(uint2*)(outh + jj * 4) = p;
    }
}

// ===========================================================================
// Kernel 4: output projection via tf32 mma.sync (K=384 = 3 accumulated
// chunks), 512 threads / 16 warps; A staged from fp16 g_attn; fused
// residual + warp-per-row LayerNorm.
// ===========================================================================
__global__ void __launch_bounds__(512, 1)
outproj_mma_kernel(const float* __restrict__ X,
                   const float* __restrict__ Wo,
                   const float* __restrict__ gamma,
                   const float* __restrict__ beta,
                   float* __restrict__ out) {
    extern __shared__ uint32_t sm[];
    uint32_t* As = sm;                 // [128][LDP]
    uint32_t* Ws = sm + 128 * LDP;     // [128][LDP]
    float* Ys = (float*)sm;            // reuse As after GEMM
    int tid = threadIdx.x, lane = tid & 31, wid = tid >> 5;
    int mw = wid & 3, nw = wid >> 2;
    int g = lane >> 2, q = lane & 3;
    int row0 = blockIdx.x * 128;

    const uint32_t* abase = As + (mw * 32 + g) * LDP + q;
    const uint32_t* bbase = Ws + (nw * 32 + g) * LDP + q;

    float acc[2][4][4];
    #pragma unroll
    for (int t2 = 0; t2 < 2; t2++)
        #pragma unroll
        for (int j = 0; j < 4; j++)
            #pragma unroll
            for (int e = 0; e < 4; e++) acc[t2][j][e] = 0.f;

    for (int t = 0; t < NT; t++) {
        __syncthreads();
        // A from fp16 g_attn (8 halfs per 16B load)
        for (int i = tid; i < 128 * 16; i += 512) {
            int r = i >> 4, k = (i & 15) << 3;
            uint4 a = *(const uint4*)(&g_attn[t][row0 + r][k]);
            float2 f0 = __half22float2(*(__half2*)&a.x);
            float2 f1 = __half22float2(*(__half2*)&a.y);
            float2 f2 = __half22float2(*(__half2*)&a.z);
            float2 f3 = __half22float2(*(__half2*)&a.w);
            uint32_t* d = As + r * LDP + k;
            d[0] = f2tf32(f0.x); d[1] = f2tf32(f0.y);
            d[2] = f2tf32(f1.x); d[3] = f2tf32(f1.y);
            d[4] = f2tf32(f2.x); d[5] = f2tf32(f2.y);
            d[6] = f2tf32(f3.x); d[7] = f2tf32(f3.y);
        }
        for (int i = tid; i < 128 * 32; i += 512) {
            int r = i >> 5, k = (i & 31) << 2;
            float4 w = *(const float4*)(Wo + (size_t)r * (NT * DM) + t * DM + k);
            uint32_t* d2 = Ws + r * LDP + k;
            d2[0] = f2tf32(w.x); d2[1] = f2tf32(w.y); d2[2] = f2tf32(w.z); d2[3] = f2tf32(w.w);
        }
        __syncthreads();
        #pragma unroll 4
        for (int ks = 0; ks < 16; ks++) {
            int k0 = ks * 8;
            uint32_t a[2][4];
            #pragma unroll
            for (int t2 = 0; t2 < 2; t2++) {
                const uint32_t* ap = abase + t2 * 16 * LDP + k0;
                a[t2][0] = ap[0]; a[t2][1] = ap[8 * LDP];
                a[t2][2] = ap[4]; a[t2][3] = ap[8 * LDP + 4];
            }
            #pragma unroll
            for (int j = 0; j < 4; j++) {
                const uint32_t* bp = bbase + j * 8 * LDP + k0;
                uint32_t b[2]; b[0] = bp[0]; b[1] = bp[4];
                mma8(acc[0][j], a[0], b);
                mma8(acc[1][j], a[1], b);
            }
        }
    }
    __syncthreads();
    #pragma unroll
    for (int t2 = 0; t2 < 2; t2++) {
        int r = mw * 32 + t2 * 16 + g;
        #pragma unroll
        for (int j = 0; j < 4; j++) {
            int c = nw * 32 + j * 8 + q * 2;
            *(float2*)(Ys + r * LDP + c)       = make_float2(acc[t2][j][0], acc[t2][j][1]);
            *(float2*)(Ys + (r + 8) * LDP + c) = make_float2(acc[t2][j][2], acc[t2][j][3]);
        }
    }
    __syncthreads();
    for (int r = wid; r < 128; r += 16) {
        float4 y  = *(float4*)(Ys + r * LDP + lane * 4);
        float4 xv = *(const float4*)(X + (size_t)(row0 + r) * DM + lane * 4);
        float v0 = y.x + xv.x, v1 = y.y + xv.y, v2 = y.z + xv.z, v3 = y.w + xv.w;
        float s  = v0 + v1 + v2 + v3;
        float s2 = v0 * v0 + v1 * v1 + v2 * v2 + v3 * v3;
        #pragma unroll
        for (int off = 16; off; off >>= 1) {
            s  += __shfl_xor_sync(0xffffffffu, s,  off);
            s2 += __shfl_xor_sync(0xffffffffu, s2, off);
        }
        float mu = s * (1.f / DM);
        float var = s2 * (1.f / DM) - mu * mu;
        float rs = rsqrtf(var + 1e-5f);
        float4 gv = *(const float4*)(gamma + lane * 4);
        float4 bv = *(const float4*)(beta + lane * 4);
        float4 res = make_float4((v0 - mu) * rs * gv.x + bv.x,
                                 (v1 - mu) * rs * gv.y + bv.y,
                                 (v2 - mu) * rs * gv.z + bv.z,
                                 (v3 - mu) * rs * gv.w + bv.w);
        *(float4*)(out + (size_t)(row0 + r) * DM + lane * 4) = res;
    }
}

// ===========================================================================
extern "C" void kernel_launch(void* const* d_in, const int* in_sizes, int n_in,
                              void* d_out, int out_size) {
    const float* inputs = (const float*)d_in[0];
    const float* tm     = (const float*)d_in[2];
    const float* Wq     = (const float*)d_in[3];
    const float* Wk     = (const float*)d_in[4];
    const float* Wv     = (const float*)d_in[5];
    const float* Wo     = (const float*)d_in[6];
    const float* gamma  = (const float*)d_in[7];
    const float* beta   = (const float*)d_in[8];
    float* out = (float*)d_out;

    int smem_qkv  = (64 + 128) * LDP * (int)sizeof(float);  // 101376
    int smem_attn = 2 * 512 * 32 * (int)sizeof(float);      // 131072
    int smem_out  = 2 * 128 * LDP * (int)sizeof(float);     // 135168
    cudaFuncSetAttribute(qkv_mma_kernel,     cudaFuncAttributeMaxDynamicSharedMemorySize, smem_qkv);
    cudaFuncSetAttribute(attn_kernel,        cudaFuncAttributeMaxDynamicSharedMemorySize, smem_attn);
    cudaFuncSetAttribute(outproj_mma_kernel, cudaFuncAttributeMaxDynamicSharedMemorySize, smem_out);

    count_kernel<<<(NT * NN * 32 + 255) / 256, 256>>>(tm);
    rank_kernel<<<NT, NN>>>();
    fill_kernel<<<(NT * NN * 32 + 255) / 256, 256>>>(tm);
    qkv_mma_kernel<<<dim3(NROWS / 64, 9), 256, smem_qkv>>>(inputs, Wq, Wk, Wv);
    attn_kernel<<<dim3(NH, NT * NB * NP), 512, smem_attn>>>();
    outproj_mma_kernel<<<NROWS / 128, 512, smem_out>>>(inputs, Wo, gamma, beta, out);
}

// round 11
// speedup vs baseline: 1.1125x; 1.1125x over previous
#include <cuda_runtime.h>
#include <cuda_fp16.h>
#include <math.h>
#include <stdint.h>

#define NB 4
#define NP 8
#define NN 512
#define DM 128
#define NH 4
#define DK 32
#define NT 3
#define NROWS (NB*NP*NN)     // 16384
#define MAXNNZ 128
#define LDP 132              // smem row stride (floats) for tf32 GEMM tiles
#define LDH 68               // smem row stride (uint32 = half2) for fp16 tiles

// Scratch (device globals). fp16 intermediates to halve HBM traffic.
__device__ __half g_qkv[9][NROWS][DM];   // [t*3 + {Q,K,V}][row][d]
__device__ __half g_attn[NT][NROWS][DM]; // per-t attention output (fp16)
__device__ int    g_nnz[NT][NN];
__device__ int    g_colsT[NT][MAXNNZ][NN];   // [t][i][n] -> coalesced over n
__device__ float  g_valsT[NT][MAXNNZ][NN];

__constant__ int c_which[NT] = {0, 1, 3};

// ---------------------------------------------------------------------------
__device__ __forceinline__ uint32_t f2tf32(float f) {
    uint32_t r; asm("cvt.rna.tf32.f32 %0, %1;" : "=r"(r) : "f"(f)); return r;
}
__device__ __forceinline__ uint32_t pack_h2(float a, float b) {
    __half2 h = __floats2half2_rn(a, b);
    return *(uint32_t*)&h;
}
// m16n8k8 tf32 MMA, D += A*B (row x col)
__device__ __forceinline__ void mma8(float d[4], const uint32_t a[4], const uint32_t b[2]) {
    asm volatile("mma.sync.aligned.m16n8k8.row.col.f32.tf32.tf32.f32 "
        "{%0,%1,%2,%3}, {%4,%5,%6,%7}, {%8,%9}, {%0,%1,%2,%3};"
        : "+f"(d[0]), "+f"(d[1]), "+f"(d[2]), "+f"(d[3])
        : "r"(a[0]), "r"(a[1]), "r"(a[2]), "r"(a[3]), "r"(b[0]), "r"(b[1]));
}
// m16n8k16 fp16 MMA, fp32 accum, D += A*B (row x col)
__device__ __forceinline__ void mma16(float d[4], const uint32_t a[4], const uint32_t b[2]) {
    asm volatile("mma.sync.aligned.m16n8k16.row.col.f32.f16.f16.f32 "
        "{%0,%1,%2,%3}, {%4,%5,%6,%7}, {%8,%9}, {%0,%1,%2,%3};"
        : "+f"(d[0]), "+f"(d[1]), "+f"(d[2]), "+f"(d[3])
        : "r"(a[0]), "r"(a[1]), "r"(a[2]), "r"(a[3]), "r"(b[0]), "r"(b[1]));
}

// ===========================================================================
// Kernel 1: build transposed CSR of the selected transition matrices.
// Warp per row n; ballot compaction; [t][i][n] layout (coalesced over n).
// ===========================================================================
__global__ void build_csr_kernel(const float* __restrict__ tmall) {
    int wg   = (blockIdx.x * blockDim.x + threadIdx.x) >> 5;
    int lane = threadIdx.x & 31;
    if (wg >= NT * NN) return;
    int t = wg / NN, n = wg % NN;
    const float* row = tmall + ((size_t)c_which[t] * NN + n) * NN;
    int cnt = 0;
    for (int base = 0; base < NN; base += 32) {
        float v = row[base + lane];
        unsigned b = __ballot_sync(0xffffffffu, v != 0.0f);
        if (v != 0.0f) {
            int pos = cnt + __popc(b & ((1u << lane) - 1u));
            if (pos < MAXNNZ) { g_colsT[t][pos][n] = base + lane; g_valsT[t][pos][n] = v; }
        }
        cnt += __popc(b);
    }
    if (lane == 0) g_nnz[t][n] = cnt < MAXNNZ ? cnt : MAXNNZ;
}

// ===========================================================================
// Kernel 2: QKV projections via fp16 mma.sync m16n8k16 (fp32 accumulate).
// grid = (256 tiles, 9 slots); 256 threads / 8 warps (2m x 4n of 32x32);
// 3 CTAs/SM (51KB smem). Fragment loads: addr = row*LDH + q, LDH=68 ->
// (4g+q) mod 32 = lane -> conflict-free. Output stored fp16.
// ===========================================================================
__global__ void __launch_bounds__(256, 3)
qkv_mma_kernel(const float* __restrict__ X,
               const float* __restrict__ Wq,
               const float* __restrict__ Wk,
               const float* __restrict__ Wv) {
    extern __shared__ uint32_t sm[];
    uint32_t* Xh = sm;                // [64][LDH] half2 units
    uint32_t* Wh = sm + 64 * LDH;     // [128][LDH]
    int tid = threadIdx.x, lane = tid & 31, wid = tid >> 5;
    int mw = wid & 1, nw = wid >> 1;
    int g = lane >> 2, q = lane & 3;
    int slot = blockIdx.y;
    int row0 = blockIdx.x * 64;

    const float* Wb[3] = {Wq, Wk, Wv};
    const float* W = Wb[slot % 3] + (size_t)(slot / 3) * DM * DM;

    // stage X (64x128 fp32 -> fp16)
    for (int i = tid; i < 64 * 32; i += 256) {
        int r = i >> 5, k4 = (i & 31) << 2;
        float4 v = *(const float4*)(X + (size_t)(row0 + r) * DM + k4);
        uint2 p = make_uint2(pack_h2(v.x, v.y), pack_h2(v.z, v.w));
        *(uint2*)(Xh + r * LDH + (k4 >> 1)) = p;
    }
    // stage W (128x128 fp32 -> fp16)
    for (int i = tid; i < 128 * 32; i += 256) {
        int r = i >> 5, k4 = (i & 31) << 2;
        float4 v = *(const float4*)(W + (size_t)r * DM + k4);
        uint2 p = make_uint2(pack_h2(v.x, v.y), pack_h2(v.z, v.w));
        *(uint2*)(Wh + r * LDH + (k4 >> 1)) = p;
    }
    __syncthreads();

    const uint32_t* abase = Xh + (mw * 32 + g) * LDH + q;
    const uint32_t* bbase = Wh + (nw * 32 + g) * LDH + q;

    float acc[2][4][4];
    #pragma unroll
    for (int t2 = 0; t2 < 2; t2++)
        #pragma unroll
        for (int j = 0; j < 4; j++)
            #pragma unroll
            for (int e = 0; e < 4; e++) acc[t2][j][e] = 0.f;

    #pragma unroll
    for (int ks = 0; ks < 8; ks++) {       // 8 steps of k=16
        int k0 = ks * 8;                   // uint32 (half2) offset
        uint32_t a[2][4];
        #pragma unroll
        for (int t2 = 0; t2 < 2; t2++) {
            const uint32_t* ap = abase + t2 * 16 * LDH + k0;
            a[t2][0] = ap[0];            a[t2][1] = ap[8 * LDH];
            a[t2][2] = ap[4];            a[t2][3] = ap[8 * LDH + 4];
        }
        #pragma unroll
        for (int j = 0; j < 4; j++) {
            const uint32_t* bp = bbase + j * 8 * LDH + k0;
            uint32_t b[2]; b[0] = bp[0]; b[1] = bp[4];
            mma16(acc[0][j], a[0], b);
            mma16(acc[1][j], a[1], b);
        }
    }
    __half* outh = &g_qkv[slot][row0][0];
    #pragma unroll
    for (int t2 = 0; t2 < 2; t2++) {
        int r = mw * 32 + t2 * 16 + g;
        #pragma unroll
        for (int j = 0; j < 4; j++) {
            int c = nw * 32 + j * 8 + q * 2;
            *(uint32_t*)(outh + (size_t)r * DM + c)       = pack_h2(acc[t2][j][0], acc[t2][j][1]);
            *(uint32_t*)(outh + (size_t)(r + 8) * DM + c) = pack_h2(acc[t2][j][2], acc[t2][j][3]);
        }
    }
}

// ===========================================================================
// Kernel 3: sparse-masked attention. Block = (t,bp,h), 512 threads, one per
// query row n (NO rank sort -- twice measured harmful). K/V read fp16 from
// g_qkv into the R4 fp32 SMEM layout (stride-32, lane-rotated float4 reads ->
// deterministic 4-phase crossbar). Direct exp; scale folded into Q; coalesced
// transposed CSR; fp16 output.
// ===========================================================================
__global__ void __launch_bounds__(512, 1)
attn_kernel() {
    extern __shared__ float smf[];
    float* Ks = smf;               // [512][32]
    float* Vs = smf + 512 * 32;    // [512][32]
    int tid = threadIdx.x;
    int h = blockIdx.x;
    int t = blockIdx.y >> 5, bp = blockIdx.y & 31;

    const __half* Kg = &g_qkv[t * 3 + 1][(size_t)bp * NN][0];
    const __half* Vg = &g_qkv[t * 3 + 2][(size_t)bp * NN][0];
    for (int i = tid; i < 512 * 4; i += 512) {
        int m = i >> 2, c = i & 3;
        uint4 kk = *(const uint4*)(Kg + (size_t)m * DM + h * DK + c * 8);
        float2 f0 = __half22float2(*(__half2*)&kk.x);
        float2 f1 = __half22float2(*(__half2*)&kk.y);
        float2 f2 = __half22float2(*(__half2*)&kk.z);
        float2 f3 = __half22float2(*(__half2*)&kk.w);
        *(float4*)(Ks + m * 32 + c * 8)     = make_float4(f0.x, f0.y, f1.x, f1.y);
        *(float4*)(Ks + m * 32 + c * 8 + 4) = make_float4(f2.x, f2.y, f3.x, f3.y);
        uint4 vv = *(const uint4*)(Vg + (size_t)m * DM + h * DK + c * 8);
        f0 = __half22float2(*(__half2*)&vv.x);
        f1 = __half22float2(*(__half2*)&vv.y);
        f2 = __half22float2(*(__half2*)&vv.z);
        f3 = __half22float2(*(__half2*)&vv.w);
        *(float4*)(Vs + m * 32 + c * 8)     = make_float4(f0.x, f0.y, f1.x, f1.y);
        *(float4*)(Vs + m * 32 + c * 8 + 4) = make_float4(f2.x, f2.y, f3.x, f3.y);
    }
    __syncthreads();

    int n = tid;
    int gn = bp * NN + n;
    int rot = tid & 7;
    const float scale = 0.17677669529663687f;   // 1/sqrt(32), folded into Q
    float4 qr[8];
    const __half* Qg = &g_qkv[t * 3 + 0][gn][h * DK];
    #pragma unroll
    for (int j = 0; j < 8; j++) {
        int jj = (j + rot) & 7;
        uint2 qv = *(const uint2*)(Qg + jj * 4);
        float2 a = __half22float2(*(__half2*)&qv.x);
        float2 b = __half22float2(*(__half2*)&qv.y);
        qr[j] = make_float4(a.x * scale, a.y * scale, b.x * scale, b.y * scale);
    }
    int cnt = g_nnz[t][n];
    float Z = 0.f;
    float4 av[8];
    #pragma unroll
    for (int j = 0; j < 8; j++) av[j] = make_float4(0.f, 0.f, 0.f, 0.f);

    for (int i = 0; i < cnt; i++) {
        int m = g_colsT[t][i][n];        // coalesced: lanes = consecutive n
        float tv = g_valsT[t][i][n];
        const float* kb = Ks + m * 32;
        float s = 0.f;
        #pragma unroll
        for (int j = 0; j < 8; j++) {
            int jj = (j + rot) & 7;
            float4 k4 = *(const float4*)(kb + jj * 4);
            s += qr[j].x * k4.x + qr[j].y * k4.y + qr[j].z * k4.z + qr[j].w * k4.w;
        }
        float e = __expf(s);
        Z += e;
        float we = tv * e;
        const float* vb = Vs + m * 32;
        #pragma unroll
        for (int j = 0; j < 8; j++) {
            int jj = (j + rot) & 7;
            float4 v4 = *(const float4*)(vb + jj * 4);
            av[j].x += we * v4.x;
            av[j].y += we * v4.y;
            av[j].z += we * v4.z;
            av[j].w += we * v4.w;
        }
    }
    float inv = 1.f / Z;
    __half* outh = &g_attn[t][gn][h * DK];
    #pragma unroll
    for (int j = 0; j < 8; j++) {
        int jj = (j + rot) & 7;
        uint2 p = make_uint2(pack_h2(av[j].x * inv, av[j].y * inv),
                             pack_h2(av[j].z * inv, av[j].w * inv));
        *(uint2*)(outh + jj * 4) = p;
    }
}

// ===========================================================================
// Kernel 4: output projection via tf32 mma.sync (K=384 = 3 accumulated
// chunks), 512 threads / 16 warps; A staged from fp16 g_attn; fused
// residual + warp-per-row LayerNorm.
// ===========================================================================
__global__ void __launch_bounds__(512, 1)
outproj_mma_kernel(const float* __restrict__ X,
                   const float* __restrict__ Wo,
                   const float* __restrict__ gamma,
                   const float* __restrict__ beta,
                   float* __restrict__ out) {
    extern __shared__ uint32_t sm[];
    uint32_t* As = sm;                 // [128][LDP]
    uint32_t* Ws = sm + 128 * LDP;     // [128][LDP]
    float* Ys = (float*)sm;            // reuse As after GEMM
    int tid = threadIdx.x, lane = tid & 31, wid = tid >> 5;
    int mw = wid & 3, nw = wid >> 2;
    int g = lane >> 2, q = lane & 3;
    int row0 = blockIdx.x * 128;

    const uint32_t* abase = As + (mw * 32 + g) * LDP + q;
    const uint32_t* bbase = Ws + (nw * 32 + g) * LDP + q;

    float acc[2][4][4];
    #pragma unroll
    for (int t2 = 0; t2 < 2; t2++)
        #pragma unroll
        for (int j = 0; j < 4; j++)
            #pragma unroll
            for (int e = 0; e < 4; e++) acc[t2][j][e] = 0.f;

    for (int t = 0; t < NT; t++) {
        __syncthreads();
        // A from fp16 g_attn (8 halfs per 16B load)
        for (int i = tid; i < 128 * 16; i += 512) {
            int r = i >> 4, k = (i & 15) << 3;
            uint4 a = *(const uint4*)(&g_attn[t][row0 + r][k]);
            float2 f0 = __half22float2(*(__half2*)&a.x);
            float2 f1 = __half22float2(*(__half2*)&a.y);
            float2 f2 = __half22float2(*(__half2*)&a.z);
            float2 f3 = __half22float2(*(__half2*)&a.w);
            uint32_t* d = As + r * LDP + k;
            d[0] = f2tf32(f0.x); d[1] = f2tf32(f0.y);
            d[2] = f2tf32(f1.x); d[3] = f2tf32(f1.y);
            d[4] = f2tf32(f2.x); d[5] = f2tf32(f2.y);
            d[6] = f2tf32(f3.x); d[7] = f2tf32(f3.y);
        }
        for (int i = tid; i < 128 * 32; i += 512) {
            int r = i >> 5, k = (i & 31) << 2;
            float4 w = *(const float4*)(Wo + (size_t)r * (NT * DM) + t * DM + k);
            uint32_t* d2 = Ws + r * LDP + k;
            d2[0] = f2tf32(w.x); d2[1] = f2tf32(w.y); d2[2] = f2tf32(w.z); d2[3] = f2tf32(w.w);
        }
        __syncthreads();
        #pragma unroll 4
        for (int ks = 0; ks < 16; ks++) {
            int k0 = ks * 8;
            uint32_t a[2][4];
            #pragma unroll
            for (int t2 = 0; t2 < 2; t2++) {
                const uint32_t* ap = abase + t2 * 16 * LDP + k0;
                a[t2][0] = ap[0]; a[t2][1] = ap[8 * LDP];
                a[t2][2] = ap[4]; a[t2][3] = ap[8 * LDP + 4];
            }
            #pragma unroll
            for (int j = 0; j < 4; j++) {
                const uint32_t* bp = bbase + j * 8 * LDP + k0;
                uint32_t b[2]; b[0] = bp[0]; b[1] = bp[4];
                mma8(acc[0][j], a[0], b);
                mma8(acc[1][j], a[1], b);
            }
        }
    }
    __syncthreads();
    #pragma unroll
    for (int t2 = 0; t2 < 2; t2++) {
        int r = mw * 32 + t2 * 16 + g;
        #pragma unroll
        for (int j = 0; j < 4; j++) {
            int c = nw * 32 + j * 8 + q * 2;
            *(float2*)(Ys + r * LDP + c)       = make_float2(acc[t2][j][0], acc[t2][j][1]);
            *(float2*)(Ys + (r + 8) * LDP + c) = make_float2(acc[t2][j][2], acc[t2][j][3]);
        }
    }
    __syncthreads();
    for (int r = wid; r < 128; r += 16) {
        float4 y  = *(float4*)(Ys + r * LDP + lane * 4);
        float4 xv = *(const float4*)(X + (size_t)(row0 + r) * DM + lane * 4);
        float v0 = y.x + xv.x, v1 = y.y + xv.y, v2 = y.z + xv.z, v3 = y.w + xv.w;
        float s  = v0 + v1 + v2 + v3;
        float s2 = v0 * v0 + v1 * v1 + v2 * v2 + v3 * v3;
        #pragma unroll
        for (int off = 16; off; off >>= 1) {
            s  += __shfl_xor_sync(0xffffffffu, s,  off);
            s2 += __shfl_xor_sync(0xffffffffu, s2, off);
        }
        float mu = s * (1.f / DM);
        float var = s2 * (1.f / DM) - mu * mu;
        float rs = rsqrtf(var + 1e-5f);
        float4 gv = *(const float4*)(gamma + lane * 4);
        float4 bv = *(const float4*)(beta + lane * 4);
        float4 res = make_float4((v0 - mu) * rs * gv.x + bv.x,
                                 (v1 - mu) * rs * gv.y + bv.y,
                                 (v2 - mu) * rs * gv.z + bv.z,
                                 (v3 - mu) * rs * gv.w + bv.w);
        *(float4*)(out + (size_t)(row0 + r) * DM + lane * 4) = res;
    }
}

// ===========================================================================
extern "C" void kernel_launch(void* const* d_in, const int* in_sizes, int n_in,
                              void* d_out, int out_size) {
    const float* inputs = (const float*)d_in[0];
    const float* tm     = (const float*)d_in[2];
    const float* Wq     = (const float*)d_in[3];
    const float* Wk     = (const float*)d_in[4];
    const float* Wv     = (const float*)d_in[5];
    const float* Wo     = (const float*)d_in[6];
    const float* gamma  = (const float*)d_in[7];
    const float* beta   = (const float*)d_in[8];
    float* out = (float*)d_out;

    int smem_qkv  = (64 + 128) * LDH * (int)sizeof(uint32_t); // 52224
    int smem_attn = 2 * 512 * 32 * (int)sizeof(float);        // 131072
    int smem_out  = 2 * 128 * LDP * (int)sizeof(float);       // 135168
    cudaFuncSetAttribute(qkv_mma_kernel,     cudaFuncAttributeMaxDynamicSharedMemorySize, smem_qkv);
    cudaFuncSetAttribute(attn_kernel,        cudaFuncAttributeMaxDynamicSharedMemorySize, smem_attn);
    cudaFuncSetAttribute(outproj_mma_kernel, cudaFuncAttributeMaxDynamicSharedMemorySize, smem_out);

    build_csr_kernel<<<(NT * NN * 32 + 255) / 256, 256>>>(tm);
    qkv_mma_kernel<<<dim3(NROWS / 64, 9), 256, smem_qkv>>>(inputs, Wq, Wk, Wv);
    attn_kernel<<<dim3(NH, NT * NB * NP), 512, smem_attn>>>();
    outproj_mma_kernel<<<NROWS / 128, 512, smem_out>>>(inputs, Wo, gamma, beta, out);
}